// round 12
// baseline (speedup 1.0000x reference)
#include <cuda_runtime.h>
#include <cuda_fp16.h>
#include <cstdint>

// ---------------- problem constants ----------------
#define NB   32
#define IC   64
#define OCH  128
#define HH   128
#define WW   128
#define OH   126
#define OW   126

// smem: two x buffers + two weight PAIR buffers (2 taps each), rows stride XSTR
#define XSTR     72
#define SX_ROWS  130
#define SX_BYTES (SX_ROWS * XSTR * 2)            // 18720
#define TAPB     (OCH * XSTR * 2)                // 18432 per tap
#define PAIRB    (2 * TAPB)                      // 36864
#define XB0      0
#define XB1      SX_BYTES
#define PB0      (2 * SX_BYTES)
#define PB1      (2 * SX_BYTES + PAIRB)
#define SMEM_BYTES (2 * SX_BYTES + 2 * PAIRB)    // 111168

// pre-converted fp16 weights: g_wh[kk][oc][ic/2] as half2 (row = oc, 64 halves)
__device__ __half2 g_wh[9 * OCH * (IC / 2)];
// pre-transposed fp16 x: g_xh[n][h][w][ic/2]  (ic contiguous)
__device__ __half2 g_xh[(size_t)NB * HH * WW * (IC / 2)];

// merged prologue: x transpose+convert, plus weight convert in 9 blocks
__global__ void prep_kernel(const float* __restrict__ x,
                            const float* __restrict__ wg) {
    __shared__ __half s[128 * 66];
    const int h = blockIdx.x, n = blockIdx.y, tid = threadIdx.x;
    const float* src = x + ((size_t)n * IC * HH + h) * WW;
    #pragma unroll
    for (int i = 0; i < 32; i++) {
        int idx = tid + i * 256;
        int ic = idx >> 7, w = idx & 127;
        s[w * 66 + ic] = __float2half_rn(src[(size_t)ic * (HH * WW) + w]);
    }
    __syncthreads();
    __half2* dst = g_xh + ((size_t)(n * HH + h)) * (WW * 32);
    #pragma unroll
    for (int i = 0; i < 16; i++) {
        int idx = tid + i * 256;
        int w = idx >> 5, icp = idx & 31;
        dst[w * 32 + icp] = *(__half2*)&s[w * 66 + 2 * icp];
    }
    // weight convert: blocks (h<9, n==0), tap kk = h
    if (n == 0 && h < 9) {
        const int kk = h;
        #pragma unroll
        for (int i = 0; i < 16; i++) {
            int idx = tid + i * 256;            // 0..4095 over oc*32+icp
            int oc  = idx >> 5;
            int ic  = (idx & 31) * 2;
            g_wh[kk * (OCH * 32) + idx] =
                __floats2half2_rn(wg[(oc * IC + ic) * 9 + kk],
                                  wg[(oc * IC + ic + 1) * 9 + kk]);
        }
    }
}

__device__ __forceinline__ uint32_t smem_u32(const void* p) {
    uint32_t a;
    asm("{ .reg .u64 t; cvta.to.shared.u64 t, %1; cvt.u32.u64 %0, t; }"
        : "=r"(a) : "l"(p));
    return a;
}
__device__ __forceinline__ void cp16(uint32_t dst, const void* src) {
    asm volatile("cp.async.cg.shared.global [%0], [%1], 16;"
                 :: "r"(dst), "l"(src));
}
__device__ __forceinline__ void ldsm_x4(uint32_t& r0, uint32_t& r1,
                                        uint32_t& r2, uint32_t& r3,
                                        uint32_t addr) {
    asm volatile("ldmatrix.sync.aligned.m8n8.x4.shared.b16 {%0,%1,%2,%3}, [%4];"
                 : "=r"(r0), "=r"(r1), "=r"(r2), "=r"(r3) : "r"(addr));
}
__device__ __forceinline__ void hmma16816(float* c, const uint32_t* a,
                                          uint32_t b0, uint32_t b1) {
    asm volatile(
        "mma.sync.aligned.m16n8k16.row.col.f32.f16.f16.f32 "
        "{%0,%1,%2,%3}, {%4,%5,%6,%7}, {%8,%9}, {%0,%1,%2,%3};"
        : "+f"(c[0]), "+f"(c[1]), "+f"(c[2]), "+f"(c[3])
        : "r"(a[0]), "r"(a[1]), "r"(a[2]), "r"(a[3]), "r"(b0), "r"(b1));
}

__global__ void __launch_bounds__(256, 2)
conv_hmma_kernel(const float* __restrict__ bias,
                 float* __restrict__ out)
{
    extern __shared__ char smem[];
    const uint32_t sbase = smem_u32(smem);

    const int tid  = threadIdx.x;
    const int lane = tid & 31;
    const int warp = tid >> 5;
    const int g    = lane >> 2;      // group id 0..7
    const int t    = lane & 3;       // thread in group

    const int warp_m = warp & 1;     // 2 warps over M=128 (64 each)
    const int warp_n = warp >> 1;    // 4 warps over N=128 (32 each)

    const int oh = blockIdx.x;
    const int n  = blockIdx.y;

    float c[4][4][4];                // [m-tile][n-tile][reg]
    #pragma unroll
    for (int i = 0; i < 4; i++)
        #pragma unroll
        for (int j = 0; j < 4; j++)
            #pragma unroll
            for (int r = 0; r < 4; r++)
                c[i][j][r] = 0.f;

    // zero halo rows w=128,129 of BOTH x buffers (64 halves = 32 u32 per row)
    if (tid < 128) {
        int bsel = tid >> 6;
        int r    = (tid >> 5) & 1;
        int cc   = tid & 31;
        *(uint32_t*)(smem + (bsel ? XB1 : XB0) +
                     (128 + r) * (XSTR * 2) + cc * 4) = 0;
    }

    const uint32_t xoff[3] = {XB0, XB1, XB0};    // indexed by kh
    const uint32_t poff[2] = {PB0, PB1};
    auto stage_x = [&](uint32_t off, int ih) {
        const __half* xr = (const __half*)g_xh +
                           ((size_t)(n * HH + ih)) * (WW * IC);
        #pragma unroll
        for (int i = 0; i < 4; i++) {
            int idx = tid + i * 256;
            int w = idx >> 3, cc = idx & 7;
            cp16(sbase + off + (uint32_t)((w * XSTR + cc * 8) * 2),
                 xr + w * IC + cc * 8);
        }
    };
    // stage 'cnt' taps starting at tap kk into pair buffer 'off'
    auto stage_taps = [&](uint32_t off, int kk, int cnt) {
        const __half* wr = (const __half*)g_wh + (size_t)kk * (OCH * IC);
        for (int q = 0; q < cnt; q++) {
            #pragma unroll
            for (int i = 0; i < 4; i++) {
                int idx = tid + i * 256;
                int oc = idx >> 3, cc = idx & 7;
                cp16(sbase + off + (uint32_t)(q * TAPB +
                         (oc * XSTR + cc * 8) * 2),
                     wr + (q * OCH + oc) * IC + cc * 8);
            }
        }
    };

    // ldmatrix per-lane invariant offsets (bytes)
    const int l7 = lane & 7;
    const uint32_t a_lane =
        (uint32_t)(((l7 + ((lane >> 3) & 1) * 8) * XSTR + ((lane >> 4) & 1) * 8) * 2);
    const uint32_t b_lane =
        (uint32_t)(((l7 + ((lane >> 4) & 1) * 8) * XSTR + ((lane >> 3) & 1) * 8) * 2);

    // ---- prologue: x rows oh, oh+1 + weight pair0 (taps 0,1) in group0
    stage_x(XB0, oh);
    stage_x(XB1, oh + 1);
    stage_taps(PB0, 0, 2);
    asm volatile("cp.async.commit_group;" ::: "memory");

    // ---- 5 regions: {0,1} {2,3} {4,5} {6,7} {8}; ONE barrier per region
    #pragma unroll
    for (int rg = 0; rg < 5; rg++) {
        asm volatile("cp.async.wait_group 0;" ::: "memory");
        __syncthreads();

        // stage next region (1 ahead) into the other pair buffer; WAR-safe:
        // that buffer was last read in region rg-1 and all warps passed the
        // barrier above.
        if (rg < 4) {
            const int kk_next = 2 * (rg + 1);
            if (rg == 2) stage_x(XB0, oh + 2);   // XB0 last read in region 1
            stage_taps(poff[(rg + 1) & 1], kk_next, (kk_next == 8) ? 1 : 2);
        }
        asm volatile("cp.async.commit_group;" ::: "memory");

        const int ntap = (rg == 4) ? 1 : 2;
        #pragma unroll
        for (int q = 0; q < 2; q++) {
            if (q >= ntap) break;
            const int kk = 2 * rg + q;
            const int kh = kk / 3, kw = kk % 3;
            const uint32_t aBase = sbase + xoff[kh] + a_lane +
                                   (uint32_t)((warp_m * 64 + kw) * XSTR * 2);
            const uint32_t bBase = sbase + poff[rg & 1] + b_lane +
                                   (uint32_t)(q * TAPB + warp_n * 32 * XSTR * 2);

            #pragma unroll
            for (int ks = 0; ks < 4; ks++) {
                uint32_t a[4][4];
                #pragma unroll
                for (int i = 0; i < 4; i++)
                    ldsm_x4(a[i][0], a[i][1], a[i][2], a[i][3],
                            aBase + (uint32_t)((i * 16 * XSTR + ks * 16) * 2));

                #pragma unroll
                for (int jp = 0; jp < 2; jp++) {
                    uint32_t b0, b1, b2, b3;
                    ldsm_x4(b0, b1, b2, b3,
                            bBase + (uint32_t)((jp * 16 * XSTR + ks * 16) * 2));
                    #pragma unroll
                    for (int i = 0; i < 4; i++) {
                        hmma16816(c[i][jp * 2],     a[i], b0, b1);
                        hmma16816(c[i][jp * 2 + 1], a[i], b2, b3);
                    }
                }
            }
        }
    }

    // ---- epilogue: bias, -0.7, Mish ----
    #pragma unroll
    for (int j = 0; j < 4; j++) {
        const int oc0 = warp_n * 32 + j * 8 + 2 * t;
        const float b0 = bias[oc0]     - 0.7f;
        const float b1 = bias[oc0 + 1] - 0.7f;
        #pragma unroll
        for (int i = 0; i < 4; i++) {
            #pragma unroll
            for (int r = 0; r < 4; r++) {
                const int m  = warp_m * 64 + i * 16 + g + ((r & 2) ? 8 : 0);
                if (m >= OW) continue;
                const int oc = oc0 + (r & 1);
                float v = c[i][j][r] + ((r & 1) ? b1 : b0);
                float e = __expf(fminf(v, 15.f));
                float s = 1.f + e; s = s * s;
                out[((size_t)(n * OCH + oc) * OH + oh) * OW + m] =
                    v * __fdividef(s - 1.f, s + 1.f);
            }
        }
    }
}

extern "C" void kernel_launch(void* const* d_in, const int* in_sizes, int n_in,
                              void* d_out, int out_size) {
    const float* x  = (const float*)d_in[0];
    const float* w  = (const float*)d_in[1];
    const float* b  = (const float*)d_in[2];
    float* out      = (float*)d_out;

    {
        dim3 tg(HH, NB);
        prep_kernel<<<tg, 256>>>(x, w);
    }

    cudaFuncSetAttribute(conv_hmma_kernel,
                         cudaFuncAttributeMaxDynamicSharedMemorySize, SMEM_BYTES);
    dim3 grid(OH, NB);   // 126 x 32 CTAs, one (n, oh) each
    conv_hmma_kernel<<<grid, 256, SMEM_BYTES>>>(b, out);
}

// round 13
// speedup vs baseline: 1.0421x; 1.0421x over previous
#include <cuda_runtime.h>
#include <cuda_fp16.h>
#include <cstdint>

// ---------------- problem constants ----------------
#define NB   32
#define IC   64
#define OCH  128
#define HH   128
#define WW   128
#define OH   126
#define OW   126

// smem: two x buffers + two weight PAIR buffers (2 taps each), rows stride XSTR
#define XSTR     72
#define SX_ROWS  130
#define SX_BYTES (SX_ROWS * XSTR * 2)            // 18720
#define TAPB     (OCH * XSTR * 2)                // 18432 per tap
#define PAIRB    (2 * TAPB)                      // 36864
#define XB0      0
#define XB1      SX_BYTES
#define PB0      (2 * SX_BYTES)
#define PB1      (2 * SX_BYTES + PAIRB)
#define SMEM_BYTES (2 * SX_BYTES + 2 * PAIRB)    // 111168

// pre-converted fp16 weights: g_wh[kk][oc][ic/2] as half2 (row = oc, 64 halves)
__device__ __half2 g_wh[9 * OCH * (IC / 2)];
// pre-transposed fp16 x: g_xh[n][h][w][ic/2]  (ic contiguous)
__device__ __half2 g_xh[(size_t)NB * HH * WW * (IC / 2)];

// merged prologue: x transpose+convert (packed F2FP), weight convert in 9 blocks
__global__ void prep_kernel(const float* __restrict__ x,
                            const float* __restrict__ wg) {
    __shared__ __half s[128 * 66];
    const int h = blockIdx.x, n = blockIdx.y, tid = threadIdx.x;
    const float* src = x + ((size_t)n * IC * HH + h) * WW;
    // phase 1: load ic-pairs, pack to half2, store pair at s[w*66 + 2*icp]
    #pragma unroll
    for (int i = 0; i < 16; i++) {
        int idx = tid + i * 256;          // 0..4095
        int icp = idx >> 7;               // ic pair 0..31
        int w   = idx & 127;
        float v0 = src[(size_t)(2 * icp)     * (HH * WW) + w];
        float v1 = src[(size_t)(2 * icp + 1) * (HH * WW) + w];
        *(__half2*)&s[w * 66 + 2 * icp] = __floats2half2_rn(v0, v1);
    }
    __syncthreads();
    __half2* dst = g_xh + ((size_t)(n * HH + h)) * (WW * 32);
    #pragma unroll
    for (int i = 0; i < 16; i++) {
        int idx = tid + i * 256;
        int w = idx >> 5, icp = idx & 31;
        dst[w * 32 + icp] = *(__half2*)&s[w * 66 + 2 * icp];
    }
    // weight convert: blocks (h<9, n==0), tap kk = h
    if (n == 0 && h < 9) {
        const int kk = h;
        #pragma unroll
        for (int i = 0; i < 16; i++) {
            int idx = tid + i * 256;            // 0..4095 over oc*32+icp
            int oc  = idx >> 5;
            int ic  = (idx & 31) * 2;
            g_wh[kk * (OCH * 32) + idx] =
                __floats2half2_rn(wg[(oc * IC + ic) * 9 + kk],
                                  wg[(oc * IC + ic + 1) * 9 + kk]);
        }
    }
}

__device__ __forceinline__ uint32_t smem_u32(const void* p) {
    uint32_t a;
    asm("{ .reg .u64 t; cvta.to.shared.u64 t, %1; cvt.u32.u64 %0, t; }"
        : "=r"(a) : "l"(p));
    return a;
}
__device__ __forceinline__ void cp16(uint32_t dst, const void* src) {
    asm volatile("cp.async.cg.shared.global [%0], [%1], 16;"
                 :: "r"(dst), "l"(src));
}
__device__ __forceinline__ void ldsm_x4(uint32_t& r0, uint32_t& r1,
                                        uint32_t& r2, uint32_t& r3,
                                        uint32_t addr) {
    asm volatile("ldmatrix.sync.aligned.m8n8.x4.shared.b16 {%0,%1,%2,%3}, [%4];"
                 : "=r"(r0), "=r"(r1), "=r"(r2), "=r"(r3) : "r"(addr));
}
__device__ __forceinline__ void hmma16816(float* c, const uint32_t* a,
                                          uint32_t b0, uint32_t b1) {
    asm volatile(
        "mma.sync.aligned.m16n8k16.row.col.f32.f16.f16.f32 "
        "{%0,%1,%2,%3}, {%4,%5,%6,%7}, {%8,%9}, {%0,%1,%2,%3};"
        : "+f"(c[0]), "+f"(c[1]), "+f"(c[2]), "+f"(c[3])
        : "r"(a[0]), "r"(a[1]), "r"(a[2]), "r"(a[3]), "r"(b0), "r"(b1));
}
__device__ __forceinline__ float frcp(float v) {
    float r;
    asm("rcp.approx.f32 %0, %1;" : "=f"(r) : "f"(v));
    return r;
}

__global__ void __launch_bounds__(256, 2)
conv_hmma_kernel(const float* __restrict__ bias,
                 float* __restrict__ out)
{
    extern __shared__ char smem[];
    const uint32_t sbase = smem_u32(smem);

    const int tid  = threadIdx.x;
    const int lane = tid & 31;
    const int warp = tid >> 5;
    const int g    = lane >> 2;      // group id 0..7
    const int t    = lane & 3;       // thread in group

    const int warp_m = warp & 1;     // 2 warps over M=128 (64 each)
    const int warp_n = warp >> 1;    // 4 warps over N=128 (32 each)

    const int oh = blockIdx.x;
    const int n  = blockIdx.y;

    float c[4][4][4];                // [m-tile][n-tile][reg]
    #pragma unroll
    for (int i = 0; i < 4; i++)
        #pragma unroll
        for (int j = 0; j < 4; j++)
            #pragma unroll
            for (int r = 0; r < 4; r++)
                c[i][j][r] = 0.f;

    // zero halo rows w=128,129 of BOTH x buffers (64 halves = 32 u32 per row)
    if (tid < 128) {
        int bsel = tid >> 6;
        int r    = (tid >> 5) & 1;
        int cc   = tid & 31;
        *(uint32_t*)(smem + (bsel ? XB1 : XB0) +
                     (128 + r) * (XSTR * 2) + cc * 4) = 0;
    }

    const uint32_t xoff[3] = {XB0, XB1, XB0};    // indexed by kh
    const uint32_t poff[2] = {PB0, PB1};
    auto stage_x = [&](uint32_t off, int ih) {
        const __half* xr = (const __half*)g_xh +
                           ((size_t)(n * HH + ih)) * (WW * IC);
        #pragma unroll
        for (int i = 0; i < 4; i++) {
            int idx = tid + i * 256;
            int w = idx >> 3, cc = idx & 7;
            cp16(sbase + off + (uint32_t)((w * XSTR + cc * 8) * 2),
                 xr + w * IC + cc * 8);
        }
    };
    // stage 'cnt' taps starting at tap kk into pair buffer 'off'
    auto stage_taps = [&](uint32_t off, int kk, int cnt) {
        const __half* wr = (const __half*)g_wh + (size_t)kk * (OCH * IC);
        for (int q = 0; q < cnt; q++) {
            #pragma unroll
            for (int i = 0; i < 4; i++) {
                int idx = tid + i * 256;
                int oc = idx >> 3, cc = idx & 7;
                cp16(sbase + off + (uint32_t)(q * TAPB +
                         (oc * XSTR + cc * 8) * 2),
                     wr + (q * OCH + oc) * IC + cc * 8);
            }
        }
    };

    // ldmatrix per-lane invariant offsets (bytes)
    const int l7 = lane & 7;
    const uint32_t a_lane =
        (uint32_t)(((l7 + ((lane >> 3) & 1) * 8) * XSTR + ((lane >> 4) & 1) * 8) * 2);
    const uint32_t b_lane =
        (uint32_t)(((l7 + ((lane >> 4) & 1) * 8) * XSTR + ((lane >> 3) & 1) * 8) * 2);

    // ---- prologue (critical wait minimized): x row oh + taps{0,1} only.
    // XB1 (row oh+1) is first read in region 1 -> staged inside region 0.
    stage_x(XB0, oh);
    stage_taps(PB0, 0, 2);
    asm volatile("cp.async.commit_group;" ::: "memory");

    // ---- 5 regions: {0,1} {2,3} {4,5} {6,7} {8}; ONE barrier per region
    #pragma unroll
    for (int rg = 0; rg < 5; rg++) {
        asm volatile("cp.async.wait_group 0;" ::: "memory");
        __syncthreads();

        // stage next region (1 ahead) into the other pair buffer; WAR-safe:
        // that buffer was last read in region rg-1 and all warps passed the
        // barrier above.
        if (rg < 4) {
            const int kk_next = 2 * (rg + 1);
            if (rg == 0) stage_x(XB1, oh + 1);   // first read in region 1
            if (rg == 2) stage_x(XB0, oh + 2);   // XB0 last read in region 1
            stage_taps(poff[(rg + 1) & 1], kk_next, (kk_next == 8) ? 1 : 2);
        }
        asm volatile("cp.async.commit_group;" ::: "memory");

        const int ntap = (rg == 4) ? 1 : 2;
        #pragma unroll
        for (int q = 0; q < 2; q++) {
            if (q >= ntap) break;
            const int kk = 2 * rg + q;
            const int kh = kk / 3, kw = kk % 3;
            const uint32_t aBase = sbase + xoff[kh] + a_lane +
                                   (uint32_t)((warp_m * 64 + kw) * XSTR * 2);
            const uint32_t bBase = sbase + poff[rg & 1] + b_lane +
                                   (uint32_t)(q * TAPB + warp_n * 32 * XSTR * 2);

            #pragma unroll
            for (int ks = 0; ks < 4; ks++) {
                uint32_t a[4][4];
                #pragma unroll
                for (int i = 0; i < 4; i++)
                    ldsm_x4(a[i][0], a[i][1], a[i][2], a[i][3],
                            aBase + (uint32_t)((i * 16 * XSTR + ks * 16) * 2));

                #pragma unroll
                for (int jp = 0; jp < 2; jp++) {
                    uint32_t b0, b1, b2, b3;
                    ldsm_x4(b0, b1, b2, b3,
                            bBase + (uint32_t)((jp * 16 * XSTR + ks * 16) * 2));
                    #pragma unroll
                    for (int i = 0; i < 4; i++) {
                        hmma16816(c[i][jp * 2],     a[i], b0, b1);
                        hmma16816(c[i][jp * 2 + 1], a[i], b2, b3);
                    }
                }
            }
        }
    }

    // ---- epilogue: bias, -0.7, Mish = v*n/(n+2), n=e(e+2); paired rcp ----
    #pragma unroll
    for (int j = 0; j < 4; j++) {
        const int oc0 = warp_n * 32 + j * 8 + 2 * t;
        const float b0 = bias[oc0]     - 0.7f;
        const float b1 = bias[oc0 + 1] - 0.7f;
        #pragma unroll
        for (int i = 0; i < 4; i++) {
            #pragma unroll
            for (int pp = 0; pp < 4; pp += 2) {
                const int m = warp_m * 64 + i * 16 + g + ((pp & 2) ? 8 : 0);
                if (m >= OW) continue;
                float v0 = c[i][j][pp]     + b0;
                float v1 = c[i][j][pp + 1] + b1;
                float e0 = __expf(fminf(v0, 15.f));
                float e1 = __expf(fminf(v1, 15.f));
                float n0 = e0 * (e0 + 2.f);
                float n1 = e1 * (e1 + 2.f);
                float d0 = n0 + 2.f, d1 = n1 + 2.f;
                float rr = frcp(d0 * d1);
                float m0 = v0 * n0 * (rr * d1);
                float m1 = v1 * n1 * (rr * d0);
                float* ob = out + ((size_t)(n * OCH + oc0) * OH + oh) * OW + m;
                ob[0]                    = m0;
                ob[(size_t)(OH * OW)]    = m1;
            }
        }
    }
}

extern "C" void kernel_launch(void* const* d_in, const int* in_sizes, int n_in,
                              void* d_out, int out_size) {
    const float* x  = (const float*)d_in[0];
    const float* w  = (const float*)d_in[1];
    const float* b  = (const float*)d_in[2];
    float* out      = (float*)d_out;

    {
        dim3 tg(HH, NB);
        prep_kernel<<<tg, 256>>>(x, w);
    }

    cudaFuncSetAttribute(conv_hmma_kernel,
                         cudaFuncAttributeMaxDynamicSharedMemorySize, SMEM_BYTES);
    dim3 grid(OH, NB);   // 126 x 32 CTAs, one (n, oh) each
    conv_hmma_kernel<<<grid, 256, SMEM_BYTES>>>(b, out);
}

// round 14
// speedup vs baseline: 1.0458x; 1.0035x over previous
#include <cuda_runtime.h>
#include <cuda_fp16.h>
#include <cstdint>

// ---------------- problem constants ----------------
#define NB   32
#define IC   64
#define OCH  128
#define HH   128
#define WW   128
#define OH   126
#define OW   126

// smem: two x buffers + two weight PAIR buffers (2 taps each), rows stride XSTR
#define XSTR     72
#define SX_ROWS  130
#define SX_BYTES (SX_ROWS * XSTR * 2)            // 18720
#define TAPB     (OCH * XSTR * 2)                // 18432 per tap
#define PAIRB    (2 * TAPB)                      // 36864
#define XB0      0
#define XB1      SX_BYTES
#define PB0      (2 * SX_BYTES)
#define PB1      (2 * SX_BYTES + PAIRB)
#define SMEM_BYTES (2 * SX_BYTES + 2 * PAIRB)    // 111168

// pre-converted fp16 weights: g_wh[kk][oc][ic/2] as half2 (row = oc, 64 halves)
__device__ __half2 g_wh[9 * OCH * (IC / 2)];

// tiny weight-convert kernel (9 blocks)
__global__ void wt_half_kernel(const float* __restrict__ wg) {
    const int kk = blockIdx.x, tid = threadIdx.x;
    #pragma unroll
    for (int i = 0; i < 16; i++) {
        int idx = tid + i * 256;            // 0..4095 over oc*32+icp
        int oc  = idx >> 5;
        int ic  = (idx & 31) * 2;
        g_wh[kk * (OCH * 32) + idx] =
            __floats2half2_rn(wg[(oc * IC + ic) * 9 + kk],
                              wg[(oc * IC + ic + 1) * 9 + kk]);
    }
}

__device__ __forceinline__ uint32_t smem_u32(const void* p) {
    uint32_t a;
    asm("{ .reg .u64 t; cvta.to.shared.u64 t, %1; cvt.u32.u64 %0, t; }"
        : "=r"(a) : "l"(p));
    return a;
}
__device__ __forceinline__ void cp16(uint32_t dst, const void* src) {
    asm volatile("cp.async.cg.shared.global [%0], [%1], 16;"
                 :: "r"(dst), "l"(src));
}
__device__ __forceinline__ void ldsm_x4(uint32_t& r0, uint32_t& r1,
                                        uint32_t& r2, uint32_t& r3,
                                        uint32_t addr) {
    asm volatile("ldmatrix.sync.aligned.m8n8.x4.shared.b16 {%0,%1,%2,%3}, [%4];"
                 : "=r"(r0), "=r"(r1), "=r"(r2), "=r"(r3) : "r"(addr));
}
__device__ __forceinline__ void hmma16816(float* c, const uint32_t* a,
                                          uint32_t b0, uint32_t b1) {
    asm volatile(
        "mma.sync.aligned.m16n8k16.row.col.f32.f16.f16.f32 "
        "{%0,%1,%2,%3}, {%4,%5,%6,%7}, {%8,%9}, {%0,%1,%2,%3};"
        : "+f"(c[0]), "+f"(c[1]), "+f"(c[2]), "+f"(c[3])
        : "r"(a[0]), "r"(a[1]), "r"(a[2]), "r"(a[3]), "r"(b0), "r"(b1));
}
__device__ __forceinline__ float frcp(float v) {
    float r;
    asm("rcp.approx.f32 %0, %1;" : "=f"(r) : "f"(v));
    return r;
}

__global__ void __launch_bounds__(256, 2)
conv_hmma_kernel(const float* __restrict__ x,
                 const float* __restrict__ bias,
                 float* __restrict__ out)
{
    extern __shared__ char smem[];
    const uint32_t sbase = smem_u32(smem);

    const int tid  = threadIdx.x;
    const int lane = tid & 31;
    const int warp = tid >> 5;
    const int g    = lane >> 2;      // group id 0..7
    const int t    = lane & 3;       // thread in group

    const int warp_m = warp & 1;     // 2 warps over M=128 (64 each)
    const int warp_n = warp >> 1;    // 4 warps over N=128 (32 each)

    const int oh = blockIdx.x;
    const int n  = blockIdx.y;

    float c[4][4][4];                // [m-tile][n-tile][reg]
    #pragma unroll
    for (int i = 0; i < 4; i++)
        #pragma unroll
        for (int j = 0; j < 4; j++)
            #pragma unroll
            for (int r = 0; r < 4; r++)
                c[i][j][r] = 0.f;

    // zero halo rows w=128,129 of BOTH x buffers (64 halves = 32 u32 per row)
    if (tid < 128) {
        int bsel = tid >> 6;
        int r    = (tid >> 5) & 1;
        int cc   = tid & 31;
        *(uint32_t*)(smem + (bsel ? XB1 : XB0) +
                     (128 + r) * (XSTR * 2) + cc * 4) = 0;
    }

    const uint32_t xoff[3] = {XB0, XB1, XB0};    // indexed by kh
    const uint32_t poff[2] = {PB0, PB1};

    // in-main x staging: LDG float pairs -> pack fp16 -> STS.
    // Per thread: w = tid&127 fixed, icp = (tid>>7) + 2i  -> all-immediate offsets.
    const int st_w    = tid & 127;
    const int st_icp0 = tid >> 7;
    auto stage_xc = [&](uint32_t off, int ih) {
        const float* xr = x + ((size_t)n * IC * HH + ih) * WW + st_w;
        char* sdst = smem + off + (st_w * XSTR + 2 * st_icp0) * 2;
        #pragma unroll
        for (int i = 0; i < 16; i++) {
            const int icp = st_icp0 + 2 * i;
            float v0 = xr[(size_t)(2 * icp)     * (HH * WW)];
            float v1 = xr[(size_t)(2 * icp + 1) * (HH * WW)];
            *(__half2*)(sdst + 8 * i) = __floats2half2_rn(v0, v1);
        }
    };
    // stage 'cnt' weight taps starting at tap kk into pair buffer 'off'
    auto stage_taps = [&](uint32_t off, int kk, int cnt) {
        const __half* wr = (const __half*)g_wh + (size_t)kk * (OCH * IC);
        for (int q = 0; q < cnt; q++) {
            #pragma unroll
            for (int i = 0; i < 4; i++) {
                int idx = tid + i * 256;
                int oc = idx >> 3, cc = idx & 7;
                cp16(sbase + off + (uint32_t)(q * TAPB +
                         (oc * XSTR + cc * 8) * 2),
                     wr + (q * OCH + oc) * IC + cc * 8);
            }
        }
    };

    // ldmatrix per-lane invariant offsets (bytes)
    const int l7 = lane & 7;
    const uint32_t a_lane =
        (uint32_t)(((l7 + ((lane >> 3) & 1) * 8) * XSTR + ((lane >> 4) & 1) * 8) * 2);
    const uint32_t b_lane =
        (uint32_t)(((l7 + ((lane >> 4) & 1) * 8) * XSTR + ((lane >> 3) & 1) * 8) * 2);

    // ---- prologue: weights taps{0,1} via cp.async; x row oh converted inline
    stage_taps(PB0, 0, 2);
    asm volatile("cp.async.commit_group;" ::: "memory");
    stage_xc(XB0, oh);

    // ---- 5 regions: {0,1} {2,3} {4,5} {6,7} {8}; ONE barrier per region
    #pragma unroll
    for (int rg = 0; rg < 5; rg++) {
        asm volatile("cp.async.wait_group 0;" ::: "memory");
        __syncthreads();

        // stage next region (1 ahead); WAR-safe: the target pair buffer was
        // last read in region rg-1 and all warps passed the barrier above.
        if (rg < 4) {
            const int kk_next = 2 * (rg + 1);
            stage_taps(poff[(rg + 1) & 1], kk_next, (kk_next == 8) ? 1 : 2);
            asm volatile("cp.async.commit_group;" ::: "memory");
            if (rg == 0) stage_xc(XB1, oh + 1);   // first read in region 1
            if (rg == 2) stage_xc(XB0, oh + 2);   // XB0 last read in region 1
        } else {
            asm volatile("cp.async.commit_group;" ::: "memory");
        }

        const int ntap = (rg == 4) ? 1 : 2;
        #pragma unroll
        for (int q = 0; q < 2; q++) {
            if (q >= ntap) break;
            const int kk = 2 * rg + q;
            const int kh = kk / 3, kw = kk % 3;
            const uint32_t aBase = sbase + xoff[kh] + a_lane +
                                   (uint32_t)((warp_m * 64 + kw) * XSTR * 2);
            const uint32_t bBase = sbase + poff[rg & 1] + b_lane +
                                   (uint32_t)(q * TAPB + warp_n * 32 * XSTR * 2);

            #pragma unroll
            for (int ks = 0; ks < 4; ks++) {
                uint32_t a[4][4];
                #pragma unroll
                for (int i = 0; i < 4; i++)
                    ldsm_x4(a[i][0], a[i][1], a[i][2], a[i][3],
                            aBase + (uint32_t)((i * 16 * XSTR + ks * 16) * 2));

                #pragma unroll
                for (int jp = 0; jp < 2; jp++) {
                    uint32_t b0, b1, b2, b3;
                    ldsm_x4(b0, b1, b2, b3,
                            bBase + (uint32_t)((jp * 16 * XSTR + ks * 16) * 2));
                    #pragma unroll
                    for (int i = 0; i < 4; i++) {
                        hmma16816(c[i][jp * 2],     a[i], b0, b1);
                        hmma16816(c[i][jp * 2 + 1], a[i], b2, b3);
                    }
                }
            }
        }
    }

    // ---- epilogue: bias, -0.7, Mish = v*nn/(nn+2), nn=e(e+2); paired rcp ----
    #pragma unroll
    for (int j = 0; j < 4; j++) {
        const int oc0 = warp_n * 32 + j * 8 + 2 * t;
        const float b0 = bias[oc0]     - 0.7f;
        const float b1 = bias[oc0 + 1] - 0.7f;
        #pragma unroll
        for (int i = 0; i < 4; i++) {
            #pragma unroll
            for (int pp = 0; pp < 4; pp += 2) {
                const int m = warp_m * 64 + i * 16 + g + ((pp & 2) ? 8 : 0);
                if (m >= OW) continue;
                float v0 = c[i][j][pp]     + b0;
                float v1 = c[i][j][pp + 1] + b1;
                float e0 = __expf(fminf(v0, 15.f));
                float e1 = __expf(fminf(v1, 15.f));
                float n0 = e0 * (e0 + 2.f);
                float n1 = e1 * (e1 + 2.f);
                float d0 = n0 + 2.f, d1 = n1 + 2.f;
                float rr = frcp(d0 * d1);
                float m0 = v0 * n0 * (rr * d1);
                float m1 = v1 * n1 * (rr * d0);
                float* ob = out + ((size_t)(n * OCH + oc0) * OH + oh) * OW + m;
                ob[0]                 = m0;
                ob[(size_t)(OH * OW)] = m1;
            }
        }
    }
}

extern "C" void kernel_launch(void* const* d_in, const int* in_sizes, int n_in,
                              void* d_out, int out_size) {
    const float* x  = (const float*)d_in[0];
    const float* w  = (const float*)d_in[1];
    const float* b  = (const float*)d_in[2];
    float* out      = (float*)d_out;

    wt_half_kernel<<<9, 256>>>(w);

    cudaFuncSetAttribute(conv_hmma_kernel,
                         cudaFuncAttributeMaxDynamicSharedMemorySize, SMEM_BYTES);
    dim3 grid(OH, NB);   // 126 x 32 CTAs, one (n, oh) each
    conv_hmma_kernel<<<grid, 256, SMEM_BYTES>>>(x, b, out);
}